// round 4
// baseline (speedup 1.0000x reference)
#include <cuda_runtime.h>
#include <cuda_bf16.h>

// CostGenerator: cost[b,c,d,h,w] = (w>=d) ? left[b,c,h,w] - right[b,c,h,w-d] : 0
// B=2, C=32, H=128, W=256, D=48 (f32). HBM-write-bound: 403 MB out, 16 MB in.
//
// R3 change vs R1: the d-loop is processed in groups of 4. Because w0 is
// 4-aligned, the 4 shifted windows of a group live in exactly two aligned
// float4s of the smem row -> 2x LDS.128 per 4 disparities instead of 16x
// scalar LDS. Window assembly is pure register selects (fully unrolled,
// compile-time). Smem row is left-padded by 48 floats so every vector load
// is in-bounds without branches; invalid lanes are masked by selects.
// Output stores use __stcs (streaming, no reuse).

#define B_  2
#define C_  32
#define H_  128
#define W_  256
#define D_  48
#define PAD 48                  // left pad, multiple of 4, >= D
#define ROWS_PER_BLOCK 4
#define THREADS 256             // 64 float4-lanes per row * 4 rows

__global__ __launch_bounds__(THREADS, 8)
void cost_generator_kernel(const float* __restrict__ left,
                           const float* __restrict__ right,
                           float* __restrict__ out)
{
    __shared__ float s_right[ROWS_PER_BLOCK][PAD + W_];

    const int tid = threadIdx.x;
    const int r   = tid >> 6;        // row within block: 0..3
    const int v   = tid & 63;        // float4 lane within row: 0..63
    const int w0  = v << 2;          // first w this thread owns (4-aligned)

    const int hb  = blockIdx.x % (H_ / ROWS_PER_BLOCK);
    const int bc  = blockIdx.x / (H_ / ROWS_PER_BLOCK);   // fused (b*C + c)
    const int h   = hb * ROWS_PER_BLOCK + r;

    const size_t in_off = ((size_t)bc * H_ + h) * W_;

    // Left values live in registers for the whole d-loop.
    const float4 l4 = *reinterpret_cast<const float4*>(left + in_off + w0);

    // Zero the pad (values never reach output — masked — but keep it
    // deterministic) and stage this row of right into smem.
    if (v < PAD / 4) {
        *reinterpret_cast<float4*>(&s_right[r][v << 2]) = make_float4(0.f, 0.f, 0.f, 0.f);
    }
    *reinterpret_cast<float4*>(&s_right[r][PAD + w0]) =
        *reinterpret_cast<const float4*>(right + in_off + w0);
    __syncthreads();

    const float* sr = &s_right[r][PAD];

    // Output base for d=0; each d advances by one H*W plane.
    float* op = out + (((size_t)bc * D_) * H_ + h) * W_ + w0;

    #pragma unroll
    for (int g = 0; g < D_ / 4; ++g) {
        const int i0 = w0 - 4 * g;   // 4-aligned shifted base for this group

        // Two aligned vector loads cover all 4 shifted windows of the group.
        const float4 Vhi = *reinterpret_cast<const float4*>(sr + i0);
        const float4 Vlo = *reinterpret_cast<const float4*>(sr + i0 - 4);

        float4 o;

        // d = 4g   : window {Vhi.x, Vhi.y, Vhi.z, Vhi.w}, valid if i0+e   >= 0
        o.x = (i0     >= 0) ? (l4.x - Vhi.x) : 0.f;
        o.y = (i0 + 1 >= 0) ? (l4.y - Vhi.y) : 0.f;
        o.z = (i0 + 2 >= 0) ? (l4.z - Vhi.z) : 0.f;
        o.w = (i0 + 3 >= 0) ? (l4.w - Vhi.w) : 0.f;
        __stcs(reinterpret_cast<float4*>(op), o);
        op += (size_t)H_ * W_;

        // d = 4g+1 : window {Vlo.w, Vhi.x, Vhi.y, Vhi.z}, valid if i0+e-1 >= 0
        o.x = (i0     >= 1) ? (l4.x - Vlo.w) : 0.f;
        o.y = (i0 + 1 >= 1) ? (l4.y - Vhi.x) : 0.f;
        o.z = (i0 + 2 >= 1) ? (l4.z - Vhi.y) : 0.f;
        o.w = (i0 + 3 >= 1) ? (l4.w - Vhi.z) : 0.f;
        __stcs(reinterpret_cast<float4*>(op), o);
        op += (size_t)H_ * W_;

        // d = 4g+2 : window {Vlo.z, Vlo.w, Vhi.x, Vhi.y}, valid if i0+e-2 >= 0
        o.x = (i0     >= 2) ? (l4.x - Vlo.z) : 0.f;
        o.y = (i0 + 1 >= 2) ? (l4.y - Vlo.w) : 0.f;
        o.z = (i0 + 2 >= 2) ? (l4.z - Vhi.x) : 0.f;
        o.w = (i0 + 3 >= 2) ? (l4.w - Vhi.y) : 0.f;
        __stcs(reinterpret_cast<float4*>(op), o);
        op += (size_t)H_ * W_;

        // d = 4g+3 : window {Vlo.y, Vlo.z, Vlo.w, Vhi.x}, valid if i0+e-3 >= 0
        o.x = (i0     >= 3) ? (l4.x - Vlo.y) : 0.f;
        o.y = (i0 + 1 >= 3) ? (l4.y - Vlo.z) : 0.f;
        o.z = (i0 + 2 >= 3) ? (l4.z - Vlo.w) : 0.f;
        o.w = (i0 + 3 >= 3) ? (l4.w - Vhi.x) : 0.f;
        __stcs(reinterpret_cast<float4*>(op), o);
        op += (size_t)H_ * W_;
    }
}

extern "C" void kernel_launch(void* const* d_in, const int* in_sizes, int n_in,
                              void* d_out, int out_size)
{
    const float* left  = (const float*)d_in[0];
    const float* right = (const float*)d_in[1];
    float* out = (float*)d_out;

    const int grid = B_ * C_ * (H_ / ROWS_PER_BLOCK);   // 2048 blocks
    cost_generator_kernel<<<grid, THREADS>>>(left, right, out);
}

// round 5
// speedup vs baseline: 1.2105x; 1.2105x over previous
#include <cuda_runtime.h>
#include <cuda_bf16.h>

// CostGenerator: cost[b,c,d,h,w] = (w>=d) ? left[b,c,h,w] - right[b,c,h,w-d] : 0
// B=2, C=32, H=128, W=256, D=48 (f32). HBM-write-bound: 403 MB out, 16 MB in.
//
// R4 = R3 structure (grouped-by-4 disparities, 2x LDS.128 per group, shifted
// windows assembled from registers at compile time) with ONE change:
// __stcs streaming stores reverted to plain float4 stores. R3 showed .cs
// globally throttled issue (31.7%->14.5%) and DRAM (67.5%->55.5%).

#define B_  2
#define C_  32
#define H_  128
#define W_  256
#define D_  48
#define PAD 48                  // left pad, multiple of 4, >= D
#define ROWS_PER_BLOCK 4
#define THREADS 256             // 64 float4-lanes per row * 4 rows

__global__ __launch_bounds__(THREADS, 8)
void cost_generator_kernel(const float* __restrict__ left,
                           const float* __restrict__ right,
                           float* __restrict__ out)
{
    __shared__ float s_right[ROWS_PER_BLOCK][PAD + W_];

    const int tid = threadIdx.x;
    const int r   = tid >> 6;        // row within block: 0..3
    const int v   = tid & 63;        // float4 lane within row: 0..63
    const int w0  = v << 2;          // first w this thread owns (4-aligned)

    const int hb  = blockIdx.x % (H_ / ROWS_PER_BLOCK);
    const int bc  = blockIdx.x / (H_ / ROWS_PER_BLOCK);   // fused (b*C + c)
    const int h   = hb * ROWS_PER_BLOCK + r;

    const size_t in_off = ((size_t)bc * H_ + h) * W_;

    // Left values live in registers for the whole d-loop.
    const float4 l4 = *reinterpret_cast<const float4*>(left + in_off + w0);

    // Zero the pad and stage this row of right into smem (48x reuse).
    if (v < PAD / 4) {
        *reinterpret_cast<float4*>(&s_right[r][v << 2]) = make_float4(0.f, 0.f, 0.f, 0.f);
    }
    *reinterpret_cast<float4*>(&s_right[r][PAD + w0]) =
        *reinterpret_cast<const float4*>(right + in_off + w0);
    __syncthreads();

    const float* sr = &s_right[r][PAD];

    // Output base for d=0; each d advances by one H*W plane.
    float* op = out + (((size_t)bc * D_) * H_ + h) * W_ + w0;

    #pragma unroll
    for (int g = 0; g < D_ / 4; ++g) {
        const int i0 = w0 - 4 * g;   // 4-aligned shifted base for this group

        // Two aligned vector loads cover all 4 shifted windows of the group.
        const float4 Vhi = *reinterpret_cast<const float4*>(sr + i0);
        const float4 Vlo = *reinterpret_cast<const float4*>(sr + i0 - 4);

        float4 o;

        // d = 4g   : window {Vhi.x, Vhi.y, Vhi.z, Vhi.w}, valid if i0+e   >= 0
        o.x = (i0     >= 0) ? (l4.x - Vhi.x) : 0.f;
        o.y = (i0 + 1 >= 0) ? (l4.y - Vhi.y) : 0.f;
        o.z = (i0 + 2 >= 0) ? (l4.z - Vhi.z) : 0.f;
        o.w = (i0 + 3 >= 0) ? (l4.w - Vhi.w) : 0.f;
        *reinterpret_cast<float4*>(op) = o;
        op += (size_t)H_ * W_;

        // d = 4g+1 : window {Vlo.w, Vhi.x, Vhi.y, Vhi.z}, valid if i0+e-1 >= 0
        o.x = (i0     >= 1) ? (l4.x - Vlo.w) : 0.f;
        o.y = (i0 + 1 >= 1) ? (l4.y - Vhi.x) : 0.f;
        o.z = (i0 + 2 >= 1) ? (l4.z - Vhi.y) : 0.f;
        o.w = (i0 + 3 >= 1) ? (l4.w - Vhi.z) : 0.f;
        *reinterpret_cast<float4*>(op) = o;
        op += (size_t)H_ * W_;

        // d = 4g+2 : window {Vlo.z, Vlo.w, Vhi.x, Vhi.y}, valid if i0+e-2 >= 0
        o.x = (i0     >= 2) ? (l4.x - Vlo.z) : 0.f;
        o.y = (i0 + 1 >= 2) ? (l4.y - Vlo.w) : 0.f;
        o.z = (i0 + 2 >= 2) ? (l4.z - Vhi.x) : 0.f;
        o.w = (i0 + 3 >= 2) ? (l4.w - Vhi.y) : 0.f;
        *reinterpret_cast<float4*>(op) = o;
        op += (size_t)H_ * W_;

        // d = 4g+3 : window {Vlo.y, Vlo.z, Vlo.w, Vhi.x}, valid if i0+e-3 >= 0
        o.x = (i0     >= 3) ? (l4.x - Vlo.y) : 0.f;
        o.y = (i0 + 1 >= 3) ? (l4.y - Vlo.z) : 0.f;
        o.z = (i0 + 2 >= 3) ? (l4.z - Vlo.w) : 0.f;
        o.w = (i0 + 3 >= 3) ? (l4.w - Vhi.x) : 0.f;
        *reinterpret_cast<float4*>(op) = o;
        op += (size_t)H_ * W_;
    }
}

extern "C" void kernel_launch(void* const* d_in, const int* in_sizes, int n_in,
                              void* d_out, int out_size)
{
    const float* left  = (const float*)d_in[0];
    const float* right = (const float*)d_in[1];
    float* out = (float*)d_out;

    const int grid = B_ * C_ * (H_ / ROWS_PER_BLOCK);   // 2048 blocks
    cost_generator_kernel<<<grid, THREADS>>>(left, right, out);
}